// round 8
// baseline (speedup 1.0000x reference)
#include <cuda_runtime.h>
#include <cuda_fp16.h>
#include <cstdint>
#include <cstddef>

#define N_NODES 32768
#define NPG     1024
#define HIDDEN  512
#define VBDIM   2048
#define VFDIM   512
#define EDGES   (N_NODES * 32)

// ---------------- scratch (device globals; no allocation allowed) ----------
__device__ int4   g_qb[(size_t)N_NODES * VBDIM / 16];  // int8 quantized body rows
__device__ int4   g_qf[(size_t)N_NODES * VFDIM / 16];  // int8 quantized face rows
__device__ float  g_scb[N_NODES], g_scf[N_NODES];      // per-row dequant scale (incl. L2 norm)
__device__ float2 g_y[N_NODES];                        // attention output (rank-2)
__device__ float  g_score0[N_NODES];
__device__ float  g_ssb[N_NODES], g_ssf[N_NODES];      // scale_src * s_src, premultiplied
__device__ float  g_msgb[N_NODES];
__device__ double g_stats[5];
__device__ float  g_M[4];
__device__ float  g_u0[HIDDEN], g_ub[HIDDEN], g_uf[HIDDEN];
__device__ float  g_c[3];
// edge sorting
__device__ int g_cntb[N_NODES], g_cntf[N_NODES];
__device__ int g_offb[N_NODES + 1], g_offf[N_NODES + 1];
__device__ int g_curb[N_NODES], g_curf[N_NODES];
__device__ int g_esb[EDGES], g_esf[EDGES];
__device__ int g_bsum[2][128];                         // scan block sums

// ---------------- K1: tiny weight precompute + counter zeroing -------------
__global__ void k1_precompute(
    const float* __restrict__ Wq,  const float* __restrict__ Wk,
    const float* __restrict__ Wm,  const float* __restrict__ bm,
    const float* __restrict__ Wnp, const float* __restrict__ bnp,
    const float* __restrict__ Wb_root, const float* __restrict__ Wb_msg, const float* __restrict__ bb,
    const float* __restrict__ Wf_root, const float* __restrict__ Wf_msg, const float* __restrict__ bf,
    const float* __restrict__ Wpb, const float* __restrict__ bpb,
    const float* __restrict__ Wpf, const float* __restrict__ bpf)
{
    __shared__ float red[512];
    __shared__ float w1c[32], wbm[32], wfm[32];
    const int t = threadIdx.x;

    // zero sort counters (moved here from k2)
    for (int i = t; i < N_NODES; i += 512) { g_cntb[i] = 0; g_cntf[i] = 0; }

    for (int a = 0; a < 2; a++) {
        for (int b = 0; b < 2; b++) {
            red[t] = Wq[a * HIDDEN + t] * Wk[b * HIDDEN + t];
            __syncthreads();
            for (int s = 256; s > 0; s >>= 1) {
                if (t < s) red[t] += red[t + s];
                __syncthreads();
            }
            if (t == 0) g_M[a * 2 + b] = red[0];
            __syncthreads();
        }
    }

    if (t < 32) {
        float vroot_b = 0.f, vroot_f = 0.f, vb = 0.f, vf = 0.f;
        for (int j = 0; j < 32; j++) {
            vroot_b += Wb_root[t * 32 + j] * Wpb[j];
            vroot_f += Wf_root[t * 32 + j] * Wpf[j];
            vb      += Wb_msg[t * 32 + j] * Wpb[j];
            vf      += Wf_msg[t * 32 + j] * Wpf[j];
        }
        w1c[t] = Wnp[t] + vroot_b + vroot_f;
        wbm[t] = vb;
        wfm[t] = vf;
    }
    __syncthreads();

    {
        float s0 = 0.f, sb = 0.f, sf = 0.f;
        for (int k = 0; k < 32; k++) {
            float wm = Wm[t * 32 + k];
            s0 = fmaf(wm, w1c[k], s0);
            sb = fmaf(wm, wbm[k], sb);
            sf = fmaf(wm, wfm[k], sf);
        }
        g_u0[t] = s0; g_ub[t] = sb; g_uf[t] = sf;
    }

    if (t == 0) {
        float c0 = bnp[0] + bpb[0] + bpf[0];
        float cb = 0.f, cf = 0.f;
        for (int k = 0; k < 32; k++) {
            c0 += bm[k] * w1c[k] + bb[k] * Wpb[k] + bf[k] * Wpf[k];
            cb += bm[k] * wbm[k];
            cf += bm[k] * wfm[k];
        }
        g_c[0] = c0; g_c[1] = cb; g_c[2] = cf;
    }
    if (t < 5) g_stats[t] = 0.0;
}

// ---------------- helpers ----------------------------------------------------
__device__ __forceinline__ unsigned int pack4(float4 a, float qs)
{
    int x = __float2int_rn(a.x * qs);
    int y = __float2int_rn(a.y * qs);
    int z = __float2int_rn(a.z * qs);
    int w = __float2int_rn(a.w * qs);
    return (unsigned int)((x & 0xFF) | ((y & 0xFF) << 8) | ((z & 0xFF) << 16) | ((w & 0xFF) << 24));
}

// ---------------- K3B-MEGA: body norm+quant (2 warps/row) + hist + attention
// grid = N_NODES/4 blocks x 256. Blocks [0,128) additionally run the rank-2
// attention for their graph quarter (hidden under the DRAM stream of the rest).
__global__ void __launch_bounds__(256) k3b_mega(const float* __restrict__ vis,
                                                const float* __restrict__ x,
                                                const int* __restrict__ eb,
                                                const int* __restrict__ ef, int E)
{
    __shared__ float  s_ss[8], s_mx[8];
    __shared__ float2 xs[NPG];
    __shared__ double wsum[8][5];

    const int t = threadIdx.x;
    const int tid = blockIdx.x * 256 + t;
    const int wrp = t >> 5, lane = t & 31;

    // ---- body row stream: 4 rows/block, 2 warps/row, 8 float4 per lane ----
    const int row  = blockIdx.x * 4 + (wrp >> 1);
    const int half = wrp & 1;
    const float4* rp = (const float4*)(vis + (size_t)row * VBDIM) + half * 256;
    float4 v[8];
    #pragma unroll
    for (int i = 0; i < 8; i++) v[i] = __ldcs(&rp[i * 32 + lane]);

    // ---- piggyback dst histogram (first E threads) ----
    if (tid < E) {
        atomicAdd(&g_cntb[eb[E + tid]], 1);
        atomicAdd(&g_cntf[ef[E + tid]], 1);
    }

    float ss = 0.f, mx = 0.f;
    #pragma unroll
    for (int i = 0; i < 8; i++) {
        float4 a = v[i];
        ss += a.x*a.x + a.y*a.y + a.z*a.z + a.w*a.w;
        mx = fmaxf(mx, fmaxf(fmaxf(fabsf(a.x), fabsf(a.y)), fmaxf(fabsf(a.z), fabsf(a.w))));
    }
    #pragma unroll
    for (int o = 16; o; o >>= 1) {
        ss += __shfl_xor_sync(0xffffffffu, ss, o);
        mx = fmaxf(mx, __shfl_xor_sync(0xffffffffu, mx, o));
    }
    if (lane == 0) { s_ss[wrp] = ss; s_mx[wrp] = mx; }
    __syncthreads();
    const int pair = wrp & ~1;
    const float ssT = s_ss[pair] + s_ss[pair + 1];
    const float mxT = fmaxf(fmaxf(s_mx[pair], s_mx[pair + 1]), 1e-20f);
    const float qs = 127.f / mxT;

    unsigned int* o = (unsigned int*)g_qb + (size_t)row * 512 + half * 256;
    #pragma unroll
    for (int i = 0; i < 8; i++) o[i * 32 + lane] = pack4(v[i], qs);
    if (half == 0 && lane == 0)
        g_scb[row] = mxT * rsqrtf(ssT + 1e-8f) * (1.f / 127.f);

    // ---- attention for blocks [0,128): graph g = blk>>2, quarter q = blk&3 --
    if (blockIdx.x < 128) {
        const int g = blockIdx.x >> 2;
        const int q = blockIdx.x & 3;
        const float* xg = x + (size_t)g * NPG * 2;
        for (int j = t; j < NPG; j += 256)
            xs[j] = make_float2(xg[2 * j], xg[2 * j + 1]);
        __syncthreads();

        const int i = q * 256 + t;
        const float2 xi = xs[i];
        const float inv = rsqrtf((float)HIDDEN);
        const float M00 = g_M[0], M01 = g_M[1], M10 = g_M[2], M11 = g_M[3];
        const float u0 = (xi.x * M00 + xi.y * M10) * inv;
        const float u1 = (xi.x * M01 + xi.y * M11) * inv;

        float m = -1e30f;
        for (int j = 0; j < NPG; j++) {
            float2 xj = xs[j];
            m = fmaxf(m, fmaf(u0, xj.x, u1 * xj.y));
        }
        float l = 0.f, a0 = 0.f, a1 = 0.f;
        for (int j = 0; j < NPG; j++) {
            float2 xj = xs[j];
            float s = fmaf(u0, xj.x, u1 * xj.y);
            float p = __expf(s - m);
            l += p; a0 = fmaf(p, xj.x, a0); a1 = fmaf(p, xj.y, a1);
        }
        const float y0 = a0 / l, y1 = a1 / l;
        g_y[g * NPG + i] = make_float2(y0, y1);

        float vv[5] = {y0, y1, y0 * y0, y0 * y1, y1 * y1};
        #pragma unroll
        for (int k = 0; k < 5; k++) {
            float s = vv[k];
            for (int off = 16; off; off >>= 1) s += __shfl_down_sync(0xffffffffu, s, off);
            if (lane == 0) wsum[wrp][k] = (double)s;
        }
        __syncthreads();
        if (t == 0) {
            #pragma unroll
            for (int k = 0; k < 5; k++) {
                double s = 0.0;
                for (int w = 0; w < 8; w++) s += wsum[w][k];
                atomicAdd(&g_stats[k], s);
            }
        }
    }
}

// ---------------- scanA: local exclusive scan (256 blocks x 256) -----------
__global__ void k_scanA()
{
    const int list = blockIdx.x >> 7;          // 0 body, 1 face
    const int blk  = blockIdx.x & 127;
    const int t = threadIdx.x;                 // 256
    const int idx = blk * 256 + t;
    const int* cnt = list ? g_cntf : g_cntb;
    int* off = list ? g_offf : g_offb;

    const int v = cnt[idx];
    const int lane = t & 31, wrp = t >> 5;
    int x = v;
    #pragma unroll
    for (int o = 1; o < 32; o <<= 1) {
        int y = __shfl_up_sync(0xffffffffu, x, o);
        if (lane >= o) x += y;
    }
    __shared__ int wsum[8];
    if (lane == 31) wsum[wrp] = x;
    __syncthreads();
    int wpre = 0;
    #pragma unroll
    for (int w = 0; w < 8; w++) wpre += (w < wrp) ? wsum[w] : 0;
    off[idx] = wpre + x - v;                   // local exclusive prefix
    if (t == 255) g_bsum[list][blk] = wpre + x;
}

// ---------------- scanC2: lookback over block sums + finalize off/cur ------
__global__ void k_scanC2()
{
    const int list = blockIdx.x >> 7;
    const int blk  = blockIdx.x & 127;
    const int t = threadIdx.x;
    __shared__ int spre_s;
    if (t < 32) {
        int s = 0;
        for (int i = t; i < blk; i += 32) s += g_bsum[list][i];
        #pragma unroll
        for (int o = 16; o; o >>= 1) s += __shfl_down_sync(0xffffffffu, s, o);
        if (t == 0) {
            spre_s = s;
            if (blk == 127) {
                int* off = list ? g_offf : g_offb;
                off[N_NODES] = s + g_bsum[list][127];
            }
        }
    }
    __syncthreads();
    const int spre = spre_s;
    const int idx = blk * 256 + t;
    int* off = list ? g_offf : g_offb;
    int* cur = list ? g_curf : g_curb;
    const int v = off[idx] + spre;
    off[idx] = v;
    cur[idx] = v;
}

// ---------------- K3F-MEGA: face norm+quant + edge scatter + node projections
// grid = N_NODES/8 blocks x 256 (1 warp per row; tid count == E for scatter).
__global__ void __launch_bounds__(256) k3f_mega(const float* __restrict__ vis,
                                                const int* __restrict__ eb,
                                                const int* __restrict__ ef, int E,
                                                const float* __restrict__ Wv,
                                                const float* __restrict__ gamma,
                                                const float* __restrict__ beta,
                                                const float* __restrict__ prelu_a)
{
    __shared__ float A0[HIDDEN], A1[HIDDEN], D[HIDDEN];
    __shared__ float U0[HIDDEN], UB[HIDDEN], UF[HIDDEN];

    const int t = threadIdx.x;
    const int tid = blockIdx.x * 256 + t;
    const int wrp = t >> 5, lane = t & 31;
    const int row = blockIdx.x * 8 + wrp;      // node id, one warp per node

    // ---- face row loads first (in flight during scatter/smem fill) ----
    const float4* rp = (const float4*)(vis + (size_t)row * VFDIM);
    float4 v[4];
    #pragma unroll
    for (int i = 0; i < 4; i++) v[i] = __ldcs(&rp[i * 32 + lane]);

    // ---- piggyback edge scatter (tid count == E exactly) ----
    if (tid < E) {
        const int sb = eb[tid], db = eb[E + tid];
        g_esb[atomicAdd(&g_curb[db], 1)] = sb;
        const int sf = ef[tid], df = ef[E + tid];
        g_esf[atomicAdd(&g_curf[df], 1)] = sf;
    }

    // ---- fill BN/projection smem arrays (k4's per-block setup) ----
    {
        const double invN = 1.0 / (double)N_NODES;
        const double m0 = g_stats[0] * invN, m1 = g_stats[1] * invN;
        const double C00 = g_stats[2] * invN - m0 * m0;
        const double C01 = g_stats[3] * invN - m0 * m1;
        const double C11 = g_stats[4] * invN - m1 * m1;
        for (int h = t; h < HIDDEN; h += 256) {
            const float w0 = Wv[h], w1 = Wv[HIDDEN + h];
            const float var = (float)((double)w0 * w0 * C00 + 2.0 * w0 * w1 * C01 + (double)w1 * w1 * C11);
            const float mu  = (float)((double)w0 * m0 + (double)w1 * m1);
            const float gg  = gamma[h] * rsqrtf(var + 1e-5f);
            A0[h] = w0 * gg;
            A1[h] = w1 * gg;
            D[h]  = beta[h] - mu * gg;
            U0[h] = g_u0[h]; UB[h] = g_ub[h]; UF[h] = g_uf[h];
        }
    }
    __syncthreads();

    // ---- face normalize + int8 quantize ----
    float ss = 0.f, mx = 0.f;
    #pragma unroll
    for (int i = 0; i < 4; i++) {
        float4 a = v[i];
        ss += a.x*a.x + a.y*a.y + a.z*a.z + a.w*a.w;
        mx = fmaxf(mx, fmaxf(fmaxf(fabsf(a.x), fabsf(a.y)), fmaxf(fabsf(a.z), fabsf(a.w))));
    }
    #pragma unroll
    for (int o = 16; o; o >>= 1) {
        ss += __shfl_xor_sync(0xffffffffu, ss, o);
        mx = fmaxf(mx, __shfl_xor_sync(0xffffffffu, mx, o));
    }
    mx = fmaxf(mx, 1e-20f);
    const float qs = 127.f / mx;
    unsigned int* o = (unsigned int*)g_qf + (size_t)row * 128;
    #pragma unroll
    for (int i = 0; i < 4; i++) o[i * 32 + lane] = pack4(v[i], qs);
    const float scf = mx * rsqrtf(ss + 1e-8f) * (1.f / 127.f);   // all lanes
    if (lane == 0) g_scf[row] = scf;

    // ---- per-node BN + PReLU + 3 scalar projections (warp-parallel over h) --
    {
        const float2 y = g_y[row];
        const float aa = prelu_a[0];
        float acc0 = 0.f, accb = 0.f, accf = 0.f;
        #pragma unroll
        for (int k = 0; k < 16; k++) {
            const int h = lane + k * 32;
            float hv = fmaf(A0[h], y.x, fmaf(A1[h], y.y, D[h]));
            hv = (hv >= 0.f) ? hv : aa * hv;
            acc0 = fmaf(hv, U0[h], acc0);
            accb = fmaf(hv, UB[h], accb);
            accf = fmaf(hv, UF[h], accf);
        }
        #pragma unroll
        for (int of = 16; of; of >>= 1) {
            acc0 += __shfl_down_sync(0xffffffffu, acc0, of);
            accb += __shfl_down_sync(0xffffffffu, accb, of);
            accf += __shfl_down_sync(0xffffffffu, accf, of);
        }
        if (lane == 0) {
            g_score0[row] = acc0 + g_c[0];
            g_ssb[row]    = (accb + g_c[1]) * __ldg(&g_scb[row]);
            g_ssf[row]    = (accf + g_c[2]) * scf;
        }
    }
}

// ---------------- K5: dst-grouped int8 cosine message passing --------------
template<int ROWI4, bool BODY, bool FINAL>
__global__ void k5_sorted(float* __restrict__ out)
{
    const int wid = (blockIdx.x * blockDim.x + threadIdx.x) >> 5;
    const int lane = threadIdx.x & 31;
    if (wid >= N_NODES) return;

    const int4*  __restrict__ q      = BODY ? g_qb  : g_qf;
    const int*   __restrict__ off    = BODY ? g_offb : g_offf;
    const int*   __restrict__ sorted = BODY ? g_esb : g_esf;
    const float* __restrict__ ss     = BODY ? g_ssb : g_ssf;
    const float* __restrict__ sc     = BODY ? g_scb : g_scf;

    constexpr int C = ROWI4 / 32;
    int4 dreg[C];
    #pragma unroll
    for (int c = 0; c < C; c++)
        dreg[c] = q[(size_t)wid * ROWI4 + c * 32 + lane];

    const int start = off[wid], end = off[wid + 1];
    float fl = 0.f;
    int e = start;
    for (; e + 1 < end; e += 2) {
        const int s0 = sorted[e];
        const int s1 = sorted[e + 1];
        const int4* p0 = q + (size_t)s0 * ROWI4 + lane;
        const int4* p1 = q + (size_t)s1 * ROWI4 + lane;
        int id0 = 0, id1 = 0;
        #pragma unroll
        for (int c = 0; c < C; c++) {
            int4 a = __ldcg(&p0[c * 32]);
            int4 b = __ldcg(&p1[c * 32]);
            id0 = __dp4a(a.x, dreg[c].x, id0);
            id0 = __dp4a(a.y, dreg[c].y, id0);
            id0 = __dp4a(a.z, dreg[c].z, id0);
            id0 = __dp4a(a.w, dreg[c].w, id0);
            id1 = __dp4a(b.x, dreg[c].x, id1);
            id1 = __dp4a(b.y, dreg[c].y, id1);
            id1 = __dp4a(b.z, dreg[c].z, id1);
            id1 = __dp4a(b.w, dreg[c].w, id1);
        }
        fl = fmaf((float)id0, __ldg(&ss[s0]), fl);
        fl = fmaf((float)id1, __ldg(&ss[s1]), fl);
    }
    if (e < end) {
        const int s0 = sorted[e];
        const int4* p0 = q + (size_t)s0 * ROWI4 + lane;
        int id0 = 0;
        #pragma unroll
        for (int c = 0; c < C; c++) {
            int4 a = __ldcg(&p0[c * 32]);
            id0 = __dp4a(a.x, dreg[c].x, id0);
            id0 = __dp4a(a.y, dreg[c].y, id0);
            id0 = __dp4a(a.z, dreg[c].z, id0);
            id0 = __dp4a(a.w, dreg[c].w, id0);
        }
        fl = fmaf((float)id0, __ldg(&ss[s0]), fl);
    }
    for (int o = 16; o; o >>= 1) fl += __shfl_down_sync(0xffffffffu, fl, o);
    if (lane == 0) {
        if (FINAL) {
            const float msgf = fl * sc[wid];
            const float db = (float)(g_offb[wid + 1] - g_offb[wid]);
            const float df = (float)(end - start);
            out[wid] = g_score0[wid]
                     + g_msgb[wid] / fmaxf(db, 1.0f)
                     + msgf / fmaxf(df, 1.0f);
        } else {
            g_msgb[wid] = fl * sc[wid];
        }
    }
}

// ---------------- launch ----------------------------------------------------
extern "C" void kernel_launch(void* const* d_in, const int* in_sizes, int n_in,
                              void* d_out, int out_size)
{
    const float* x        = (const float*)d_in[0];
    const float* vis_body = (const float*)d_in[1];
    const float* vis_face = (const float*)d_in[2];
    const int*   edge_b   = (const int*)d_in[3];
    const int*   edge_f   = (const int*)d_in[4];
    const int E = in_sizes[3] / 2;

    int base = 5;
    if (n_in > 5 && in_sizes[5] == 1) base = 6;
    const float* Wq      = (const float*)d_in[base + 0];
    const float* Wk      = (const float*)d_in[base + 1];
    const float* Wv      = (const float*)d_in[base + 2];
    const float* gamma   = (const float*)d_in[base + 3];
    const float* beta    = (const float*)d_in[base + 4];
    const float* prelu_a = (const float*)d_in[base + 5];
    const float* Wm      = (const float*)d_in[base + 6];
    const float* bm      = (const float*)d_in[base + 7];
    const float* Wnp     = (const float*)d_in[base + 8];
    const float* bnp     = (const float*)d_in[base + 9];
    const float* Wb_root = (const float*)d_in[base + 10];
    const float* Wb_msg  = (const float*)d_in[base + 11];
    const float* bb      = (const float*)d_in[base + 12];
    const float* Wf_root = (const float*)d_in[base + 13];
    const float* Wf_msg  = (const float*)d_in[base + 14];
    const float* bf      = (const float*)d_in[base + 15];
    const float* Wpb     = (const float*)d_in[base + 16];
    const float* bpb     = (const float*)d_in[base + 17];
    const float* Wpf     = (const float*)d_in[base + 18];
    const float* bpf     = (const float*)d_in[base + 19];

    k1_precompute<<<1, 512>>>(Wq, Wk, Wm, bm, Wnp, bnp,
                              Wb_root, Wb_msg, bb, Wf_root, Wf_msg, bf,
                              Wpb, bpb, Wpf, bpf);
    k3b_mega<<<N_NODES / 4, 256>>>(vis_body, x, edge_b, edge_f, E);  // norm+hist+attn
    k_scanA<<<256, 256>>>();
    k_scanC2<<<256, 256>>>();
    k3f_mega<<<N_NODES / 8, 256>>>(vis_face, edge_b, edge_f, E,
                                   Wv, gamma, beta, prelu_a);        // norm+scatter+proj
    k5_sorted<VBDIM / 16, true,  false><<<N_NODES / 8, 256>>>(nullptr);
    k5_sorted<VFDIM / 16, false, true ><<<N_NODES / 8, 256>>>((float*)d_out);
}

// round 9
// speedup vs baseline: 1.0990x; 1.0990x over previous
#include <cuda_runtime.h>
#include <cuda_fp16.h>
#include <cstdint>
#include <cstddef>

#define N_NODES 32768
#define NPG     1024
#define HIDDEN  512
#define VBDIM   2048
#define VFDIM   512
#define EDGES   (N_NODES * 32)

// ---------------- scratch (device globals; no allocation allowed) ----------
__device__ int4   g_qb[(size_t)N_NODES * VBDIM / 16];  // int8 quantized body rows
__device__ int4   g_qf[(size_t)N_NODES * VFDIM / 16];  // int8 quantized face rows
__device__ float  g_scb[N_NODES], g_scf[N_NODES];      // per-row dequant scale (incl. L2 norm)
__device__ float2 g_y[N_NODES];                        // attention output (rank-2)
__device__ float  g_score0[N_NODES];
__device__ float  g_ssb[N_NODES], g_ssf[N_NODES];      // scale_src * s_src, premultiplied
__device__ float  g_msgb[N_NODES], g_msgf[N_NODES];
__device__ double g_stats[5];
__device__ float  g_M[4];
__device__ float  g_u0[HIDDEN], g_ub[HIDDEN], g_uf[HIDDEN];
__device__ float  g_c[3];
// edge sorting
__device__ int g_cntb[N_NODES], g_cntf[N_NODES];
__device__ int g_offb[N_NODES + 1], g_offf[N_NODES + 1];
__device__ int g_curb[N_NODES], g_curf[N_NODES];
__device__ int g_esb[EDGES], g_esf[EDGES];
__device__ int g_bsum[2][128];                         // scan block sums

// ---------------- K1: tiny weight precompute --------------------------------
__global__ void k1_precompute(
    const float* __restrict__ Wq,  const float* __restrict__ Wk,
    const float* __restrict__ Wm,  const float* __restrict__ bm,
    const float* __restrict__ Wnp, const float* __restrict__ bnp,
    const float* __restrict__ Wb_root, const float* __restrict__ Wb_msg, const float* __restrict__ bb,
    const float* __restrict__ Wf_root, const float* __restrict__ Wf_msg, const float* __restrict__ bf,
    const float* __restrict__ Wpb, const float* __restrict__ bpb,
    const float* __restrict__ Wpf, const float* __restrict__ bpf)
{
    __shared__ float red[512];
    __shared__ float w1c[32], wbm[32], wfm[32];
    const int t = threadIdx.x;

    for (int a = 0; a < 2; a++) {
        for (int b = 0; b < 2; b++) {
            red[t] = Wq[a * HIDDEN + t] * Wk[b * HIDDEN + t];
            __syncthreads();
            for (int s = 256; s > 0; s >>= 1) {
                if (t < s) red[t] += red[t + s];
                __syncthreads();
            }
            if (t == 0) g_M[a * 2 + b] = red[0];
            __syncthreads();
        }
    }

    if (t < 32) {
        float vroot_b = 0.f, vroot_f = 0.f, vb = 0.f, vf = 0.f;
        for (int j = 0; j < 32; j++) {
            vroot_b += Wb_root[t * 32 + j] * Wpb[j];
            vroot_f += Wf_root[t * 32 + j] * Wpf[j];
            vb      += Wb_msg[t * 32 + j] * Wpb[j];
            vf      += Wf_msg[t * 32 + j] * Wpf[j];
        }
        w1c[t] = Wnp[t] + vroot_b + vroot_f;
        wbm[t] = vb;
        wfm[t] = vf;
    }
    __syncthreads();

    {
        float s0 = 0.f, sb = 0.f, sf = 0.f;
        for (int k = 0; k < 32; k++) {
            float wm = Wm[t * 32 + k];
            s0 = fmaf(wm, w1c[k], s0);
            sb = fmaf(wm, wbm[k], sb);
            sf = fmaf(wm, wfm[k], sf);
        }
        g_u0[t] = s0; g_ub[t] = sb; g_uf[t] = sf;
    }

    if (t == 0) {
        float c0 = bnp[0] + bpb[0] + bpf[0];
        float cb = 0.f, cf = 0.f;
        for (int k = 0; k < 32; k++) {
            c0 += bm[k] * w1c[k] + bb[k] * Wpb[k] + bf[k] * Wpf[k];
            cb += bm[k] * wbm[k];
            cf += bm[k] * wfm[k];
        }
        g_c[0] = c0; g_c[1] = cb; g_c[2] = cf;
    }
    if (t < 5) g_stats[t] = 0.0;
}

// ---------------- K2: rank-2 attention + counter zeroing -------------------
__global__ void k2_attn(const float* __restrict__ x)
{
    __shared__ float2 xs[NPG];
    __shared__ double wsum[8][5];
    const int g = blockIdx.x >> 2;
    const int q = blockIdx.x & 3;
    const int t = threadIdx.x;
    const float* xg = x + (size_t)g * NPG * 2;

    const int nidx = blockIdx.x * 256 + t;   // 0..32767
    g_cntb[nidx] = 0;
    g_cntf[nidx] = 0;

    for (int j = t; j < NPG; j += 256)
        xs[j] = make_float2(xg[2 * j], xg[2 * j + 1]);
    __syncthreads();

    const int i = q * 256 + t;
    const float2 xi = xs[i];
    const float inv = rsqrtf((float)HIDDEN);
    const float M00 = g_M[0], M01 = g_M[1], M10 = g_M[2], M11 = g_M[3];
    const float u0 = (xi.x * M00 + xi.y * M10) * inv;
    const float u1 = (xi.x * M01 + xi.y * M11) * inv;

    float m = -1e30f;
    for (int j = 0; j < NPG; j++) {
        float2 xj = xs[j];
        m = fmaxf(m, fmaf(u0, xj.x, u1 * xj.y));
    }
    float l = 0.f, a0 = 0.f, a1 = 0.f;
    for (int j = 0; j < NPG; j++) {
        float2 xj = xs[j];
        float s = fmaf(u0, xj.x, u1 * xj.y);
        float p = __expf(s - m);
        l += p; a0 = fmaf(p, xj.x, a0); a1 = fmaf(p, xj.y, a1);
    }
    const float y0 = a0 / l, y1 = a1 / l;
    g_y[g * NPG + i] = make_float2(y0, y1);

    float v[5] = {y0, y1, y0 * y0, y0 * y1, y1 * y1};
    const int lane = t & 31, wrp = t >> 5;
    #pragma unroll
    for (int k = 0; k < 5; k++) {
        float s = v[k];
        for (int off = 16; off; off >>= 1) s += __shfl_down_sync(0xffffffffu, s, off);
        if (lane == 0) wsum[wrp][k] = (double)s;
    }
    __syncthreads();
    if (t == 0) {
        #pragma unroll
        for (int k = 0; k < 5; k++) {
            double s = 0.0;
            for (int w = 0; w < 8; w++) s += wsum[w][k];
            atomicAdd(&g_stats[k], s);
        }
    }
}

// ---------------- helpers ----------------------------------------------------
__device__ __forceinline__ unsigned int pack4(float4 a, float qs)
{
    int x = __float2int_rn(a.x * qs);
    int y = __float2int_rn(a.y * qs);
    int z = __float2int_rn(a.z * qs);
    int w = __float2int_rn(a.w * qs);
    return (unsigned int)((x & 0xFF) | ((y & 0xFF) << 8) | ((z & 0xFF) << 16) | ((w & 0xFF) << 24));
}

// ---------------- K3B: body norm+quant, 2 warps/row, + dst histogram -------
// grid = N_NODES/4 blocks x 256 (tid count 2M > E; hist guarded).
__global__ void __launch_bounds__(256) k3b_norm(const float* __restrict__ vis,
                                                const int* __restrict__ eb,
                                                const int* __restrict__ ef, int E)
{
    __shared__ float s_ss[8], s_mx[8];
    const int t = threadIdx.x;
    const int tid = blockIdx.x * 256 + t;
    const int wrp = t >> 5, lane = t & 31;

    const int row  = blockIdx.x * 4 + (wrp >> 1);
    const int half = wrp & 1;
    const float4* rp = (const float4*)(vis + (size_t)row * VBDIM) + half * 256;
    float4 v[8];
    #pragma unroll
    for (int i = 0; i < 8; i++) v[i] = __ldcs(&rp[i * 32 + lane]);

    if (tid < E) {
        atomicAdd(&g_cntb[eb[E + tid]], 1);
        atomicAdd(&g_cntf[ef[E + tid]], 1);
    }

    float ss = 0.f, mx = 0.f;
    #pragma unroll
    for (int i = 0; i < 8; i++) {
        float4 a = v[i];
        ss += a.x*a.x + a.y*a.y + a.z*a.z + a.w*a.w;
        mx = fmaxf(mx, fmaxf(fmaxf(fabsf(a.x), fabsf(a.y)), fmaxf(fabsf(a.z), fabsf(a.w))));
    }
    #pragma unroll
    for (int o = 16; o; o >>= 1) {
        ss += __shfl_xor_sync(0xffffffffu, ss, o);
        mx = fmaxf(mx, __shfl_xor_sync(0xffffffffu, mx, o));
    }
    if (lane == 0) { s_ss[wrp] = ss; s_mx[wrp] = mx; }
    __syncthreads();
    const int pair = wrp & ~1;
    const float ssT = s_ss[pair] + s_ss[pair + 1];
    const float mxT = fmaxf(fmaxf(s_mx[pair], s_mx[pair + 1]), 1e-20f);
    const float qs = 127.f / mxT;

    unsigned int* o = (unsigned int*)g_qb + (size_t)row * 512 + half * 256;
    #pragma unroll
    for (int i = 0; i < 8; i++) o[i * 32 + lane] = pack4(v[i], qs);
    if (half == 0 && lane == 0)
        g_scb[row] = mxT * rsqrtf(ssT + 1e-8f) * (1.f / 127.f);
}

// ---------------- K3F: face norm+quant, warp/row, + edge scatter ------------
// grid = N_NODES/8 blocks x 256 (tid count == E exactly).
__global__ void __launch_bounds__(256) k3f_norm(const float* __restrict__ vis,
                                                const int* __restrict__ eb,
                                                const int* __restrict__ ef, int E)
{
    const int t = threadIdx.x;
    const int tid = blockIdx.x * 256 + t;
    const int wrp = t >> 5, lane = t & 31;
    const int row = blockIdx.x * 8 + wrp;

    const float4* rp = (const float4*)(vis + (size_t)row * VFDIM);
    float4 v[4];
    #pragma unroll
    for (int i = 0; i < 4; i++) v[i] = __ldcs(&rp[i * 32 + lane]);

    if (tid < E) {
        const int sb = eb[tid], db = eb[E + tid];
        g_esb[atomicAdd(&g_curb[db], 1)] = sb;
        const int sf = ef[tid], df = ef[E + tid];
        g_esf[atomicAdd(&g_curf[df], 1)] = sf;
    }

    float ss = 0.f, mx = 0.f;
    #pragma unroll
    for (int i = 0; i < 4; i++) {
        float4 a = v[i];
        ss += a.x*a.x + a.y*a.y + a.z*a.z + a.w*a.w;
        mx = fmaxf(mx, fmaxf(fmaxf(fabsf(a.x), fabsf(a.y)), fmaxf(fabsf(a.z), fabsf(a.w))));
    }
    #pragma unroll
    for (int o = 16; o; o >>= 1) {
        ss += __shfl_xor_sync(0xffffffffu, ss, o);
        mx = fmaxf(mx, __shfl_xor_sync(0xffffffffu, mx, o));
    }
    mx = fmaxf(mx, 1e-20f);
    const float qs = 127.f / mx;
    unsigned int* o = (unsigned int*)g_qf + (size_t)row * 128;
    #pragma unroll
    for (int i = 0; i < 4; i++) o[i * 32 + lane] = pack4(v[i], qs);
    if (lane == 0) g_scf[row] = mx * rsqrtf(ss + 1e-8f) * (1.f / 127.f);
}

// ---------------- scanA: local exclusive scan (256 blocks x 256) -----------
__global__ void k_scanA()
{
    const int list = blockIdx.x >> 7;          // 0 body, 1 face
    const int blk  = blockIdx.x & 127;
    const int t = threadIdx.x;
    const int idx = blk * 256 + t;
    const int* cnt = list ? g_cntf : g_cntb;
    int* off = list ? g_offf : g_offb;

    const int v = cnt[idx];
    const int lane = t & 31, wrp = t >> 5;
    int x = v;
    #pragma unroll
    for (int o = 1; o < 32; o <<= 1) {
        int y = __shfl_up_sync(0xffffffffu, x, o);
        if (lane >= o) x += y;
    }
    __shared__ int wsum[8];
    if (lane == 31) wsum[wrp] = x;
    __syncthreads();
    int wpre = 0;
    #pragma unroll
    for (int w = 0; w < 8; w++) wpre += (w < wrp) ? wsum[w] : 0;
    off[idx] = wpre + x - v;
    if (t == 255) g_bsum[list][blk] = wpre + x;
}

// ---------------- scanC2: lookback over block sums + finalize off/cur ------
__global__ void k_scanC2()
{
    const int list = blockIdx.x >> 7;
    const int blk  = blockIdx.x & 127;
    const int t = threadIdx.x;
    __shared__ int spre_s;
    if (t < 32) {
        int s = 0;
        for (int i = t; i < blk; i += 32) s += g_bsum[list][i];
        #pragma unroll
        for (int o = 16; o; o >>= 1) s += __shfl_down_sync(0xffffffffu, s, o);
        if (t == 0) {
            spre_s = s;
            if (blk == 127) {
                int* off = list ? g_offf : g_offb;
                off[N_NODES] = s + g_bsum[list][127];
            }
        }
    }
    __syncthreads();
    const int spre = spre_s;
    const int idx = blk * 256 + t;
    int* off = list ? g_offf : g_offb;
    int* cur = list ? g_curf : g_curb;
    const int v = off[idx] + spre;
    off[idx] = v;
    cur[idx] = v;
}

// ---------------- K4: per-node BN + PReLU + 3 scalar projections -----------
__global__ void k4_node(const float* __restrict__ Wv,
                        const float* __restrict__ gamma,
                        const float* __restrict__ beta,
                        const float* __restrict__ prelu_a)
{
    __shared__ float A0[HIDDEN], A1[HIDDEN], D[HIDDEN];
    __shared__ float U0[HIDDEN], UB[HIDDEN], UF[HIDDEN];
    const int t = threadIdx.x; // 256

    const double invN = 1.0 / (double)N_NODES;
    const double m0 = g_stats[0] * invN, m1 = g_stats[1] * invN;
    const double C00 = g_stats[2] * invN - m0 * m0;
    const double C01 = g_stats[3] * invN - m0 * m1;
    const double C11 = g_stats[4] * invN - m1 * m1;

    for (int h = t; h < HIDDEN; h += 256) {
        const float w0 = Wv[h], w1 = Wv[HIDDEN + h];
        const float var = (float)((double)w0 * w0 * C00 + 2.0 * w0 * w1 * C01 + (double)w1 * w1 * C11);
        const float mu  = (float)((double)w0 * m0 + (double)w1 * m1);
        const float gg  = gamma[h] * rsqrtf(var + 1e-5f);
        A0[h] = w0 * gg;
        A1[h] = w1 * gg;
        D[h]  = beta[h] - mu * gg;
        U0[h] = g_u0[h]; UB[h] = g_ub[h]; UF[h] = g_uf[h];
    }
    __syncthreads();

    const int n = blockIdx.x * 256 + t;
    const float2 y = g_y[n];
    const float aa = prelu_a[0];
    float acc0 = 0.f, accb = 0.f, accf = 0.f;
    #pragma unroll 8
    for (int h = 0; h < HIDDEN; h++) {
        float v = fmaf(A0[h], y.x, fmaf(A1[h], y.y, D[h]));
        v = (v >= 0.f) ? v : aa * v;
        acc0 = fmaf(v, U0[h], acc0);
        accb = fmaf(v, UB[h], accb);
        accf = fmaf(v, UF[h], accf);
    }
    g_score0[n] = acc0 + g_c[0];
    g_ssb[n]    = (accb + g_c[1]) * g_scb[n];
    g_ssf[n]    = (accf + g_c[2]) * g_scf[n];
}

// ---------------- K5 core: dst-grouped int8 cosine message passing ----------
template<int ROWI4>
__device__ __forceinline__ void k5_core(int wid, int lane,
                                        const int4*  __restrict__ q,
                                        const int*   __restrict__ off,
                                        const int*   __restrict__ sorted,
                                        const float* __restrict__ ss,
                                        const float* __restrict__ sc,
                                        float*       __restrict__ msg)
{
    constexpr int C = ROWI4 / 32;
    int4 dreg[C];
    #pragma unroll
    for (int c = 0; c < C; c++)
        dreg[c] = q[(size_t)wid * ROWI4 + c * 32 + lane];

    const int start = off[wid], end = off[wid + 1];
    float fl = 0.f;
    int e = start;
    for (; e + 1 < end; e += 2) {
        const int s0 = sorted[e];
        const int s1 = sorted[e + 1];
        const int4* p0 = q + (size_t)s0 * ROWI4 + lane;
        const int4* p1 = q + (size_t)s1 * ROWI4 + lane;
        int id0 = 0, id1 = 0;
        #pragma unroll
        for (int c = 0; c < C; c++) {
            int4 a = __ldcg(&p0[c * 32]);
            int4 b = __ldcg(&p1[c * 32]);
            id0 = __dp4a(a.x, dreg[c].x, id0);
            id0 = __dp4a(a.y, dreg[c].y, id0);
            id0 = __dp4a(a.z, dreg[c].z, id0);
            id0 = __dp4a(a.w, dreg[c].w, id0);
            id1 = __dp4a(b.x, dreg[c].x, id1);
            id1 = __dp4a(b.y, dreg[c].y, id1);
            id1 = __dp4a(b.z, dreg[c].z, id1);
            id1 = __dp4a(b.w, dreg[c].w, id1);
        }
        fl = fmaf((float)id0, __ldg(&ss[s0]), fl);
        fl = fmaf((float)id1, __ldg(&ss[s1]), fl);
    }
    if (e < end) {
        const int s0 = sorted[e];
        const int4* p0 = q + (size_t)s0 * ROWI4 + lane;
        int id0 = 0;
        #pragma unroll
        for (int c = 0; c < C; c++) {
            int4 a = __ldcg(&p0[c * 32]);
            id0 = __dp4a(a.x, dreg[c].x, id0);
            id0 = __dp4a(a.y, dreg[c].y, id0);
            id0 = __dp4a(a.z, dreg[c].z, id0);
            id0 = __dp4a(a.w, dreg[c].w, id0);
        }
        fl = fmaf((float)id0, __ldg(&ss[s0]), fl);
    }
    for (int o = 16; o; o >>= 1) fl += __shfl_down_sync(0xffffffffu, fl, o);
    if (lane == 0) msg[wid] = fl * sc[wid];
}

// Union launch: blocks [0, N/8) body, [N/8, 2N/8) face — face backfills body tail.
__global__ void __launch_bounds__(256) k5_union()
{
    const int lane = threadIdx.x & 31;
    const int gw = (blockIdx.x * 256 + threadIdx.x) >> 5;   // global warp id
    if (gw < N_NODES) {
        k5_core<VBDIM / 16>(gw, lane, g_qb, g_offb, g_esb, g_ssb, g_scb, g_msgb);
    } else {
        k5_core<VFDIM / 16>(gw - N_NODES, lane, g_qf, g_offf, g_esf, g_ssf, g_scf, g_msgf);
    }
}

// ---------------- K6: final combine ----------------------------------------
__global__ void k6_final(float* __restrict__ out)
{
    const int n = blockIdx.x * 256 + threadIdx.x;
    const float db = (float)(g_offb[n + 1] - g_offb[n]);
    const float df = (float)(g_offf[n + 1] - g_offf[n]);
    out[n] = g_score0[n]
           + g_msgb[n] / fmaxf(db, 1.0f)
           + g_msgf[n] / fmaxf(df, 1.0f);
}

// ---------------- launch ----------------------------------------------------
extern "C" void kernel_launch(void* const* d_in, const int* in_sizes, int n_in,
                              void* d_out, int out_size)
{
    const float* x        = (const float*)d_in[0];
    const float* vis_body = (const float*)d_in[1];
    const float* vis_face = (const float*)d_in[2];
    const int*   edge_b   = (const int*)d_in[3];
    const int*   edge_f   = (const int*)d_in[4];
    const int E = in_sizes[3] / 2;

    int base = 5;
    if (n_in > 5 && in_sizes[5] == 1) base = 6;
    const float* Wq      = (const float*)d_in[base + 0];
    const float* Wk      = (const float*)d_in[base + 1];
    const float* Wv      = (const float*)d_in[base + 2];
    const float* gamma   = (const float*)d_in[base + 3];
    const float* beta    = (const float*)d_in[base + 4];
    const float* prelu_a = (const float*)d_in[base + 5];
    const float* Wm      = (const float*)d_in[base + 6];
    const float* bm      = (const float*)d_in[base + 7];
    const float* Wnp     = (const float*)d_in[base + 8];
    const float* bnp     = (const float*)d_in[base + 9];
    const float* Wb_root = (const float*)d_in[base + 10];
    const float* Wb_msg  = (const float*)d_in[base + 11];
    const float* bb      = (const float*)d_in[base + 12];
    const float* Wf_root = (const float*)d_in[base + 13];
    const float* Wf_msg  = (const float*)d_in[base + 14];
    const float* bf      = (const float*)d_in[base + 15];
    const float* Wpb     = (const float*)d_in[base + 16];
    const float* bpb     = (const float*)d_in[base + 17];
    const float* Wpf     = (const float*)d_in[base + 18];
    const float* bpf     = (const float*)d_in[base + 19];

    k1_precompute<<<1, 512>>>(Wq, Wk, Wm, bm, Wnp, bnp,
                              Wb_root, Wb_msg, bb, Wf_root, Wf_msg, bf,
                              Wpb, bpb, Wpf, bpf);
    k2_attn<<<128, 256>>>(x);                                       // + zero counters
    k3b_norm<<<N_NODES / 4, 256>>>(vis_body, edge_b, edge_f, E);    // + hist
    k_scanA<<<256, 256>>>();
    k_scanC2<<<256, 256>>>();
    k3f_norm<<<N_NODES / 8, 256>>>(vis_face, edge_b, edge_f, E);    // + scatter
    k4_node<<<N_NODES / 256, 256>>>(Wv, gamma, beta, prelu_a);
    k5_union<<<N_NODES / 4, 256>>>();                               // body + face
    k6_final<<<N_NODES / 256, 256>>>((float*)d_out);
}

// round 10
// speedup vs baseline: 1.1342x; 1.0320x over previous
#include <cuda_runtime.h>
#include <cuda_fp16.h>
#include <cstdint>
#include <cstddef>

#define N_NODES 32768
#define NPG     1024
#define HIDDEN  512
#define VBDIM   2048
#define VFDIM   512
#define EDGES   (N_NODES * 32)

// ---------------- scratch (device globals; no allocation allowed) ----------
__device__ int4   g_qb[(size_t)N_NODES * VBDIM / 16];  // int8 quantized body rows
__device__ int4   g_qf[(size_t)N_NODES * VFDIM / 16];  // int8 quantized face rows
__device__ float  g_scb[N_NODES], g_scf[N_NODES];      // per-row dequant scale (incl. L2 norm)
__device__ float2 g_y[N_NODES];                        // attention output (rank-2)
__device__ float  g_score0[N_NODES];
__device__ float  g_ssb[N_NODES], g_ssf[N_NODES];      // scale_src * s_src, premultiplied
__device__ float  g_msgb[N_NODES], g_msgf[N_NODES];
__device__ double g_stats[5];
__device__ float  g_M[4];
__device__ float  g_u0[HIDDEN], g_ub[HIDDEN], g_uf[HIDDEN];
__device__ float  g_c[3];
// edge sorting
__device__ int g_cntb[N_NODES], g_cntf[N_NODES];
__device__ int g_offb[N_NODES + 1], g_offf[N_NODES + 1];
__device__ int g_curb[N_NODES], g_curf[N_NODES];
__device__ int g_esb[EDGES], g_esf[EDGES];

// ---------------- K1: tiny weight precompute + counter zeroing -------------
__global__ void k1_precompute(
    const float* __restrict__ Wq,  const float* __restrict__ Wk,
    const float* __restrict__ Wm,  const float* __restrict__ bm,
    const float* __restrict__ Wnp, const float* __restrict__ bnp,
    const float* __restrict__ Wb_root, const float* __restrict__ Wb_msg, const float* __restrict__ bb,
    const float* __restrict__ Wf_root, const float* __restrict__ Wf_msg, const float* __restrict__ bf,
    const float* __restrict__ Wpb, const float* __restrict__ bpb,
    const float* __restrict__ Wpf, const float* __restrict__ bpf)
{
    __shared__ float red[512];
    __shared__ float w1c[32], wbm[32], wfm[32];
    const int t = threadIdx.x;

    for (int i = t; i < N_NODES; i += 512) { g_cntb[i] = 0; g_cntf[i] = 0; }

    for (int a = 0; a < 2; a++) {
        for (int b = 0; b < 2; b++) {
            red[t] = Wq[a * HIDDEN + t] * Wk[b * HIDDEN + t];
            __syncthreads();
            for (int s = 256; s > 0; s >>= 1) {
                if (t < s) red[t] += red[t + s];
                __syncthreads();
            }
            if (t == 0) g_M[a * 2 + b] = red[0];
            __syncthreads();
        }
    }

    if (t < 32) {
        float vroot_b = 0.f, vroot_f = 0.f, vb = 0.f, vf = 0.f;
        for (int j = 0; j < 32; j++) {
            vroot_b += Wb_root[t * 32 + j] * Wpb[j];
            vroot_f += Wf_root[t * 32 + j] * Wpf[j];
            vb      += Wb_msg[t * 32 + j] * Wpb[j];
            vf      += Wf_msg[t * 32 + j] * Wpf[j];
        }
        w1c[t] = Wnp[t] + vroot_b + vroot_f;
        wbm[t] = vb;
        wfm[t] = vf;
    }
    __syncthreads();

    {
        float s0 = 0.f, sb = 0.f, sf = 0.f;
        for (int k = 0; k < 32; k++) {
            float wm = Wm[t * 32 + k];
            s0 = fmaf(wm, w1c[k], s0);
            sb = fmaf(wm, wbm[k], sb);
            sf = fmaf(wm, wfm[k], sf);
        }
        g_u0[t] = s0; g_ub[t] = sb; g_uf[t] = sf;
    }

    if (t == 0) {
        float c0 = bnp[0] + bpb[0] + bpf[0];
        float cb = 0.f, cf = 0.f;
        for (int k = 0; k < 32; k++) {
            c0 += bm[k] * w1c[k] + bb[k] * Wpb[k] + bf[k] * Wpf[k];
            cb += bm[k] * wbm[k];
            cf += bm[k] * wfm[k];
        }
        g_c[0] = c0; g_c[1] = cb; g_c[2] = cf;
    }
    if (t < 5) g_stats[t] = 0.0;
}

// ---------------- helpers ----------------------------------------------------
__device__ __forceinline__ unsigned int pack4(float4 a, float qs)
{
    int x = __float2int_rn(a.x * qs);
    int y = __float2int_rn(a.y * qs);
    int z = __float2int_rn(a.z * qs);
    int w = __float2int_rn(a.w * qs);
    return (unsigned int)((x & 0xFF) | ((y & 0xFF) << 8) | ((z & 0xFF) << 16) | ((w & 0xFF) << 24));
}

// ---------------- K3B: body norm+quant + dst histogram + attention ----------
// grid = 128 + N_NODES/4 blocks x 256.
// Blocks [0,128): rank-2 attention only (1st wave; hidden under DRAM stream).
// Blocks [128, ...): 4 body rows/block (2 warps/row) + guarded histogram.
__global__ void __launch_bounds__(256) k3b_mega(const float* __restrict__ vis,
                                                const float* __restrict__ x,
                                                const int* __restrict__ eb,
                                                const int* __restrict__ ef, int E)
{
    __shared__ float  s_ss[8], s_mx[8];
    __shared__ float2 xs[NPG];
    __shared__ double wsum[8][5];

    const int t = threadIdx.x;
    const int wrp = t >> 5, lane = t & 31;

    if (blockIdx.x < 128) {
        // ---- attention-only block: graph g = blk>>2, quarter q = blk&3 ----
        const int g = blockIdx.x >> 2;
        const int q = blockIdx.x & 3;
        const float* xg = x + (size_t)g * NPG * 2;
        for (int j = t; j < NPG; j += 256)
            xs[j] = make_float2(xg[2 * j], xg[2 * j + 1]);
        __syncthreads();

        const int i = q * 256 + t;
        const float2 xi = xs[i];
        const float inv = rsqrtf((float)HIDDEN);
        const float M00 = g_M[0], M01 = g_M[1], M10 = g_M[2], M11 = g_M[3];
        const float u0 = (xi.x * M00 + xi.y * M10) * inv;
        const float u1 = (xi.x * M01 + xi.y * M11) * inv;

        float m = -1e30f;
        for (int j = 0; j < NPG; j++) {
            float2 xj = xs[j];
            m = fmaxf(m, fmaf(u0, xj.x, u1 * xj.y));
        }
        float l = 0.f, a0 = 0.f, a1 = 0.f;
        for (int j = 0; j < NPG; j++) {
            float2 xj = xs[j];
            float s = fmaf(u0, xj.x, u1 * xj.y);
            float p = __expf(s - m);
            l += p; a0 = fmaf(p, xj.x, a0); a1 = fmaf(p, xj.y, a1);
        }
        const float y0 = a0 / l, y1 = a1 / l;
        g_y[g * NPG + i] = make_float2(y0, y1);

        float vv[5] = {y0, y1, y0 * y0, y0 * y1, y1 * y1};
        #pragma unroll
        for (int k = 0; k < 5; k++) {
            float s = vv[k];
            for (int off = 16; off; off >>= 1) s += __shfl_down_sync(0xffffffffu, s, off);
            if (lane == 0) wsum[wrp][k] = (double)s;
        }
        __syncthreads();
        if (t == 0) {
            #pragma unroll
            for (int k = 0; k < 5; k++) {
                double s = 0.0;
                for (int w = 0; w < 8; w++) s += wsum[w][k];
                atomicAdd(&g_stats[k], s);
            }
        }
        return;
    }

    // ---- body stream blocks ----
    const int bblk = blockIdx.x - 128;
    const int tid  = bblk * 256 + t;
    const int row  = bblk * 4 + (wrp >> 1);
    const int half = wrp & 1;
    const float4* rp = (const float4*)(vis + (size_t)row * VBDIM) + half * 256;
    float4 v[8];
    #pragma unroll
    for (int i = 0; i < 8; i++) v[i] = __ldcs(&rp[i * 32 + lane]);

    if (tid < E) {
        atomicAdd(&g_cntb[eb[E + tid]], 1);
        atomicAdd(&g_cntf[ef[E + tid]], 1);
    }

    float ss = 0.f, mx = 0.f;
    #pragma unroll
    for (int i = 0; i < 8; i++) {
        float4 a = v[i];
        ss += a.x*a.x + a.y*a.y + a.z*a.z + a.w*a.w;
        mx = fmaxf(mx, fmaxf(fmaxf(fabsf(a.x), fabsf(a.y)), fmaxf(fabsf(a.z), fabsf(a.w))));
    }
    #pragma unroll
    for (int o = 16; o; o >>= 1) {
        ss += __shfl_xor_sync(0xffffffffu, ss, o);
        mx = fmaxf(mx, __shfl_xor_sync(0xffffffffu, mx, o));
    }
    if (lane == 0) { s_ss[wrp] = ss; s_mx[wrp] = mx; }
    __syncthreads();
    const int pair = wrp & ~1;
    const float ssT = s_ss[pair] + s_ss[pair + 1];
    const float mxT = fmaxf(fmaxf(s_mx[pair], s_mx[pair + 1]), 1e-20f);
    const float qs = 127.f / mxT;

    unsigned int* o = (unsigned int*)g_qb + (size_t)row * 512 + half * 256;
    #pragma unroll
    for (int i = 0; i < 8; i++) o[i * 32 + lane] = pack4(v[i], qs);
    if (half == 0 && lane == 0)
        g_scb[row] = mxT * rsqrtf(ssT + 1e-8f) * (1.f / 127.f);
}

// ---------------- single-kernel scan (256 blocks x 256) ---------------------
// Each block: (1) directly sums all counts before its tile (coalesced),
// (2) local shuffle scan, (3) writes off/cur.
__global__ void __launch_bounds__(256) k_scan1()
{
    const int list = blockIdx.x >> 7;          // 0 body, 1 face
    const int blk  = blockIdx.x & 127;
    const int t = threadIdx.x;
    const int lane = t & 31, wrp = t >> 5;
    const int* cnt = list ? g_cntf : g_cntb;
    int* off = list ? g_offf : g_offb;
    int* cur = list ? g_curf : g_curb;

    // (1) block prefix: sum of cnt[0 .. blk*256)
    int pre = 0;
    const int lim = blk * 256;
    for (int i = t; i < lim; i += 256) pre += cnt[i];
    #pragma unroll
    for (int o = 16; o; o >>= 1) pre += __shfl_xor_sync(0xffffffffu, pre, o);
    __shared__ int wpres[8];
    if (lane == 0) wpres[wrp] = pre;
    __syncthreads();
    int spre = 0;
    #pragma unroll
    for (int w = 0; w < 8; w++) spre += wpres[w];

    // (2) local exclusive scan of this block's 256 counts
    const int idx = blk * 256 + t;
    const int v = cnt[idx];
    int x = v;
    #pragma unroll
    for (int o = 1; o < 32; o <<= 1) {
        int y = __shfl_up_sync(0xffffffffu, x, o);
        if (lane >= o) x += y;
    }
    __shared__ int wsum[8];
    if (lane == 31) wsum[wrp] = x;
    __syncthreads();
    int wpre = 0;
    #pragma unroll
    for (int w = 0; w < 8; w++) wpre += (w < wrp) ? wsum[w] : 0;

    const int val = spre + wpre + x - v;
    off[idx] = val;
    cur[idx] = val;
    if (blk == 127 && t == 255) off[N_NODES] = spre + wpre + x;
}

// ---------------- K3F: face norm+quant, warp/row, + edge scatter ------------
// grid = N_NODES/8 blocks x 256 (tid count == E exactly).
__global__ void __launch_bounds__(256) k3f_norm(const float* __restrict__ vis,
                                                const int* __restrict__ eb,
                                                const int* __restrict__ ef, int E)
{
    const int t = threadIdx.x;
    const int tid = blockIdx.x * 256 + t;
    const int wrp = t >> 5, lane = t & 31;
    const int row = blockIdx.x * 8 + wrp;

    const float4* rp = (const float4*)(vis + (size_t)row * VFDIM);
    float4 v[4];
    #pragma unroll
    for (int i = 0; i < 4; i++) v[i] = __ldcs(&rp[i * 32 + lane]);

    if (tid < E) {
        const int sb = eb[tid], db = eb[E + tid];
        g_esb[atomicAdd(&g_curb[db], 1)] = sb;
        const int sf = ef[tid], df = ef[E + tid];
        g_esf[atomicAdd(&g_curf[df], 1)] = sf;
    }

    float ss = 0.f, mx = 0.f;
    #pragma unroll
    for (int i = 0; i < 4; i++) {
        float4 a = v[i];
        ss += a.x*a.x + a.y*a.y + a.z*a.z + a.w*a.w;
        mx = fmaxf(mx, fmaxf(fmaxf(fabsf(a.x), fabsf(a.y)), fmaxf(fabsf(a.z), fabsf(a.w))));
    }
    #pragma unroll
    for (int o = 16; o; o >>= 1) {
        ss += __shfl_xor_sync(0xffffffffu, ss, o);
        mx = fmaxf(mx, __shfl_xor_sync(0xffffffffu, mx, o));
    }
    mx = fmaxf(mx, 1e-20f);
    const float qs = 127.f / mx;
    unsigned int* o = (unsigned int*)g_qf + (size_t)row * 128;
    #pragma unroll
    for (int i = 0; i < 4; i++) o[i * 32 + lane] = pack4(v[i], qs);
    if (lane == 0) g_scf[row] = mx * rsqrtf(ss + 1e-8f) * (1.f / 127.f);
}

// ---------------- K4: per-node BN + PReLU + 3 scalar projections -----------
__global__ void k4_node(const float* __restrict__ Wv,
                        const float* __restrict__ gamma,
                        const float* __restrict__ beta,
                        const float* __restrict__ prelu_a)
{
    __shared__ float A0[HIDDEN], A1[HIDDEN], D[HIDDEN];
    __shared__ float U0[HIDDEN], UB[HIDDEN], UF[HIDDEN];
    const int t = threadIdx.x; // 256

    const double invN = 1.0 / (double)N_NODES;
    const double m0 = g_stats[0] * invN, m1 = g_stats[1] * invN;
    const double C00 = g_stats[2] * invN - m0 * m0;
    const double C01 = g_stats[3] * invN - m0 * m1;
    const double C11 = g_stats[4] * invN - m1 * m1;

    for (int h = t; h < HIDDEN; h += 256) {
        const float w0 = Wv[h], w1 = Wv[HIDDEN + h];
        const float var = (float)((double)w0 * w0 * C00 + 2.0 * w0 * w1 * C01 + (double)w1 * w1 * C11);
        const float mu  = (float)((double)w0 * m0 + (double)w1 * m1);
        const float gg  = gamma[h] * rsqrtf(var + 1e-5f);
        A0[h] = w0 * gg;
        A1[h] = w1 * gg;
        D[h]  = beta[h] - mu * gg;
        U0[h] = g_u0[h]; UB[h] = g_ub[h]; UF[h] = g_uf[h];
    }
    __syncthreads();

    const int n = blockIdx.x * 256 + t;
    const float2 y = g_y[n];
    const float aa = prelu_a[0];
    float acc0 = 0.f, accb = 0.f, accf = 0.f;
    #pragma unroll 8
    for (int h = 0; h < HIDDEN; h++) {
        float v = fmaf(A0[h], y.x, fmaf(A1[h], y.y, D[h]));
        v = (v >= 0.f) ? v : aa * v;
        acc0 = fmaf(v, U0[h], acc0);
        accb = fmaf(v, UB[h], accb);
        accf = fmaf(v, UF[h], accf);
    }
    g_score0[n] = acc0 + g_c[0];
    g_ssb[n]    = (accb + g_c[1]) * g_scb[n];
    g_ssf[n]    = (accf + g_c[2]) * g_scf[n];
}

// ---------------- K5 core: dst-grouped int8 cosine message passing ----------
template<int ROWI4>
__device__ __forceinline__ void k5_core(int wid, int lane,
                                        const int4*  __restrict__ q,
                                        const int*   __restrict__ off,
                                        const int*   __restrict__ sorted,
                                        const float* __restrict__ ss,
                                        const float* __restrict__ sc,
                                        float*       __restrict__ msg)
{
    constexpr int C = ROWI4 / 32;
    int4 dreg[C];
    #pragma unroll
    for (int c = 0; c < C; c++)
        dreg[c] = q[(size_t)wid * ROWI4 + c * 32 + lane];

    const int start = off[wid], end = off[wid + 1];
    float fl = 0.f;
    int e = start;
    for (; e + 1 < end; e += 2) {
        const int s0 = sorted[e];
        const int s1 = sorted[e + 1];
        const int4* p0 = q + (size_t)s0 * ROWI4 + lane;
        const int4* p1 = q + (size_t)s1 * ROWI4 + lane;
        int id0 = 0, id1 = 0;
        #pragma unroll
        for (int c = 0; c < C; c++) {
            int4 a = __ldcg(&p0[c * 32]);
            int4 b = __ldcg(&p1[c * 32]);
            id0 = __dp4a(a.x, dreg[c].x, id0);
            id0 = __dp4a(a.y, dreg[c].y, id0);
            id0 = __dp4a(a.z, dreg[c].z, id0);
            id0 = __dp4a(a.w, dreg[c].w, id0);
            id1 = __dp4a(b.x, dreg[c].x, id1);
            id1 = __dp4a(b.y, dreg[c].y, id1);
            id1 = __dp4a(b.z, dreg[c].z, id1);
            id1 = __dp4a(b.w, dreg[c].w, id1);
        }
        fl = fmaf((float)id0, __ldg(&ss[s0]), fl);
        fl = fmaf((float)id1, __ldg(&ss[s1]), fl);
    }
    if (e < end) {
        const int s0 = sorted[e];
        const int4* p0 = q + (size_t)s0 * ROWI4 + lane;
        int id0 = 0;
        #pragma unroll
        for (int c = 0; c < C; c++) {
            int4 a = __ldcg(&p0[c * 32]);
            id0 = __dp4a(a.x, dreg[c].x, id0);
            id0 = __dp4a(a.y, dreg[c].y, id0);
            id0 = __dp4a(a.z, dreg[c].z, id0);
            id0 = __dp4a(a.w, dreg[c].w, id0);
        }
        fl = fmaf((float)id0, __ldg(&ss[s0]), fl);
    }
    for (int o = 16; o; o >>= 1) fl += __shfl_down_sync(0xffffffffu, fl, o);
    if (lane == 0) msg[wid] = fl * sc[wid];
}

// Union launch: warps [0, N) body, [N, 2N) face — face backfills body tail.
__global__ void __launch_bounds__(256) k5_union()
{
    const int lane = threadIdx.x & 31;
    const int gw = (blockIdx.x * 256 + threadIdx.x) >> 5;   // global warp id
    if (gw < N_NODES) {
        k5_core<VBDIM / 16>(gw, lane, g_qb, g_offb, g_esb, g_ssb, g_scb, g_msgb);
    } else {
        k5_core<VFDIM / 16>(gw - N_NODES, lane, g_qf, g_offf, g_esf, g_ssf, g_scf, g_msgf);
    }
}

// ---------------- K6: final combine ----------------------------------------
__global__ void k6_final(float* __restrict__ out)
{
    const int n = blockIdx.x * 256 + threadIdx.x;
    const float db = (float)(g_offb[n + 1] - g_offb[n]);
    const float df = (float)(g_offf[n + 1] - g_offf[n]);
    out[n] = g_score0[n]
           + g_msgb[n] / fmaxf(db, 1.0f)
           + g_msgf[n] / fmaxf(df, 1.0f);
}

// ---------------- launch ----------------------------------------------------
extern "C" void kernel_launch(void* const* d_in, const int* in_sizes, int n_in,
                              void* d_out, int out_size)
{
    const float* x        = (const float*)d_in[0];
    const float* vis_body = (const float*)d_in[1];
    const float* vis_face = (const float*)d_in[2];
    const int*   edge_b   = (const int*)d_in[3];
    const int*   edge_f   = (const int*)d_in[4];
    const int E = in_sizes[3] / 2;

    int base = 5;
    if (n_in > 5 && in_sizes[5] == 1) base = 6;
    const float* Wq      = (const float*)d_in[base + 0];
    const float* Wk      = (const float*)d_in[base + 1];
    const float* Wv      = (const float*)d_in[base + 2];
    const float* gamma   = (const float*)d_in[base + 3];
    const float* beta    = (const float*)d_in[base + 4];
    const float* prelu_a = (const float*)d_in[base + 5];
    const float* Wm      = (const float*)d_in[base + 6];
    const float* bm      = (const float*)d_in[base + 7];
    const float* Wnp     = (const float*)d_in[base + 8];
    const float* bnp     = (const float*)d_in[base + 9];
    const float* Wb_root = (const float*)d_in[base + 10];
    const float* Wb_msg  = (const float*)d_in[base + 11];
    const float* bb      = (const float*)d_in[base + 12];
    const float* Wf_root = (const float*)d_in[base + 13];
    const float* Wf_msg  = (const float*)d_in[base + 14];
    const float* bf      = (const float*)d_in[base + 15];
    const float* Wpb     = (const float*)d_in[base + 16];
    const float* bpb     = (const float*)d_in[base + 17];
    const float* Wpf     = (const float*)d_in[base + 18];
    const float* bpf     = (const float*)d_in[base + 19];

    k1_precompute<<<1, 512>>>(Wq, Wk, Wm, bm, Wnp, bnp,
                              Wb_root, Wb_msg, bb, Wf_root, Wf_msg, bf,
                              Wpb, bpb, Wpf, bpf);                   // + zero counters
    k3b_mega<<<128 + N_NODES / 4, 256>>>(vis_body, x, edge_b, edge_f, E); // attn + norm + hist
    k_scan1<<<256, 256>>>();
    k3f_norm<<<N_NODES / 8, 256>>>(vis_face, edge_b, edge_f, E);     // + scatter
    k4_node<<<N_NODES / 256, 256>>>(Wv, gamma, beta, prelu_a);
    k5_union<<<N_NODES / 4, 256>>>();                                // body + face
    k6_final<<<N_NODES / 256, 256>>>((float*)d_out);
}

// round 11
// speedup vs baseline: 1.1482x; 1.0123x over previous
#include <cuda_runtime.h>
#include <cuda_fp16.h>
#include <cstdint>
#include <cstddef>

#define N_NODES 32768
#define NPG     1024
#define HIDDEN  512
#define VBDIM   2048
#define VFDIM   512
#define EDGES   (N_NODES * 32)

// ---------------- scratch (device globals; no allocation allowed) ----------
__device__ int4   g_qb[(size_t)N_NODES * VBDIM / 16];  // int8 quantized body rows
__device__ int4   g_qf[(size_t)N_NODES * VFDIM / 16];  // int8 quantized face rows
__device__ float  g_scb[N_NODES], g_scf[N_NODES];      // per-row dequant scale (incl. L2 norm)
__device__ float2 g_y[N_NODES];                        // attention output (rank-2)
__device__ float  g_score0[N_NODES];
__device__ float  g_ssb[N_NODES], g_ssf[N_NODES];      // scale_src * s_src, premultiplied
__device__ float  g_msgb[N_NODES], g_msgf[N_NODES];
__device__ double g_stats[5];
__device__ float  g_M[4];
__device__ float  g_u0[HIDDEN], g_ub[HIDDEN], g_uf[HIDDEN];
__device__ float  g_c[3];
// edge sorting
__device__ int g_cntb[N_NODES], g_cntf[N_NODES];
__device__ int g_offb[N_NODES + 1], g_offf[N_NODES + 1];
__device__ int g_rkb[EDGES], g_rkf[EDGES];             // per-edge rank within dst bucket
__device__ int g_esb[EDGES], g_esf[EDGES];

// ---------------- K1: tiny weight precompute + counter zeroing -------------
__global__ void k1_precompute(
    const float* __restrict__ Wq,  const float* __restrict__ Wk,
    const float* __restrict__ Wm,  const float* __restrict__ bm,
    const float* __restrict__ Wnp, const float* __restrict__ bnp,
    const float* __restrict__ Wb_root, const float* __restrict__ Wb_msg, const float* __restrict__ bb,
    const float* __restrict__ Wf_root, const float* __restrict__ Wf_msg, const float* __restrict__ bf,
    const float* __restrict__ Wpb, const float* __restrict__ bpb,
    const float* __restrict__ Wpf, const float* __restrict__ bpf)
{
    __shared__ float red[512];
    __shared__ float w1c[32], wbm[32], wfm[32];
    const int t = threadIdx.x;

    for (int i = t; i < N_NODES; i += 512) { g_cntb[i] = 0; g_cntf[i] = 0; }

    for (int a = 0; a < 2; a++) {
        for (int b = 0; b < 2; b++) {
            red[t] = Wq[a * HIDDEN + t] * Wk[b * HIDDEN + t];
            __syncthreads();
            for (int s = 256; s > 0; s >>= 1) {
                if (t < s) red[t] += red[t + s];
                __syncthreads();
            }
            if (t == 0) g_M[a * 2 + b] = red[0];
            __syncthreads();
        }
    }

    if (t < 32) {
        float vroot_b = 0.f, vroot_f = 0.f, vb = 0.f, vf = 0.f;
        for (int j = 0; j < 32; j++) {
            vroot_b += Wb_root[t * 32 + j] * Wpb[j];
            vroot_f += Wf_root[t * 32 + j] * Wpf[j];
            vb      += Wb_msg[t * 32 + j] * Wpb[j];
            vf      += Wf_msg[t * 32 + j] * Wpf[j];
        }
        w1c[t] = Wnp[t] + vroot_b + vroot_f;
        wbm[t] = vb;
        wfm[t] = vf;
    }
    __syncthreads();

    {
        float s0 = 0.f, sb = 0.f, sf = 0.f;
        for (int k = 0; k < 32; k++) {
            float wm = Wm[t * 32 + k];
            s0 = fmaf(wm, w1c[k], s0);
            sb = fmaf(wm, wbm[k], sb);
            sf = fmaf(wm, wfm[k], sf);
        }
        g_u0[t] = s0; g_ub[t] = sb; g_uf[t] = sf;
    }

    if (t == 0) {
        float c0 = bnp[0] + bpb[0] + bpf[0];
        float cb = 0.f, cf = 0.f;
        for (int k = 0; k < 32; k++) {
            c0 += bm[k] * w1c[k] + bb[k] * Wpb[k] + bf[k] * Wpf[k];
            cb += bm[k] * wbm[k];
            cf += bm[k] * wfm[k];
        }
        g_c[0] = c0; g_c[1] = cb; g_c[2] = cf;
    }
    if (t < 5) g_stats[t] = 0.0;
}

// ---------------- helpers ----------------------------------------------------
__device__ __forceinline__ unsigned int pack4(float4 a, float qs)
{
    int x = __float2int_rn(a.x * qs);
    int y = __float2int_rn(a.y * qs);
    int z = __float2int_rn(a.z * qs);
    int w = __float2int_rn(a.w * qs);
    return (unsigned int)((x & 0xFF) | ((y & 0xFF) << 8) | ((z & 0xFF) << 16) | ((w & 0xFF) << 24));
}

// ---------------- K3B: body norm+quant + hist-with-rank + attention ----------
// grid = 128 + N_NODES/4 blocks x 256.
// Blocks [0,128): rank-2 attention only (1st wave; hidden under DRAM stream).
// Blocks [128, ...): 4 body rows/block (2 warps/row) + guarded hist+rank.
__global__ void __launch_bounds__(256) k3b_mega(const float* __restrict__ vis,
                                                const float* __restrict__ x,
                                                const int* __restrict__ eb,
                                                const int* __restrict__ ef, int E)
{
    __shared__ float  s_ss[8], s_mx[8];
    __shared__ float2 xs[NPG];
    __shared__ double wsum[8][5];

    const int t = threadIdx.x;
    const int wrp = t >> 5, lane = t & 31;

    if (blockIdx.x < 128) {
        const int g = blockIdx.x >> 2;
        const int q = blockIdx.x & 3;
        const float* xg = x + (size_t)g * NPG * 2;
        for (int j = t; j < NPG; j += 256)
            xs[j] = make_float2(xg[2 * j], xg[2 * j + 1]);
        __syncthreads();

        const int i = q * 256 + t;
        const float2 xi = xs[i];
        const float inv = rsqrtf((float)HIDDEN);
        const float M00 = g_M[0], M01 = g_M[1], M10 = g_M[2], M11 = g_M[3];
        const float u0 = (xi.x * M00 + xi.y * M10) * inv;
        const float u1 = (xi.x * M01 + xi.y * M11) * inv;

        float m = -1e30f;
        for (int j = 0; j < NPG; j++) {
            float2 xj = xs[j];
            m = fmaxf(m, fmaf(u0, xj.x, u1 * xj.y));
        }
        float l = 0.f, a0 = 0.f, a1 = 0.f;
        for (int j = 0; j < NPG; j++) {
            float2 xj = xs[j];
            float s = fmaf(u0, xj.x, u1 * xj.y);
            float p = __expf(s - m);
            l += p; a0 = fmaf(p, xj.x, a0); a1 = fmaf(p, xj.y, a1);
        }
        const float y0 = a0 / l, y1 = a1 / l;
        g_y[g * NPG + i] = make_float2(y0, y1);

        float vv[5] = {y0, y1, y0 * y0, y0 * y1, y1 * y1};
        #pragma unroll
        for (int k = 0; k < 5; k++) {
            float s = vv[k];
            for (int off = 16; off; off >>= 1) s += __shfl_down_sync(0xffffffffu, s, off);
            if (lane == 0) wsum[wrp][k] = (double)s;
        }
        __syncthreads();
        if (t == 0) {
            #pragma unroll
            for (int k = 0; k < 5; k++) {
                double s = 0.0;
                for (int w = 0; w < 8; w++) s += wsum[w][k];
                atomicAdd(&g_stats[k], s);
            }
        }
        return;
    }

    // ---- body stream blocks ----
    const int bblk = blockIdx.x - 128;
    const int tid  = bblk * 256 + t;
    const int row  = bblk * 4 + (wrp >> 1);
    const int half = wrp & 1;
    const float4* rp = (const float4*)(vis + (size_t)row * VBDIM) + half * 256;
    float4 v[8];
    #pragma unroll
    for (int i = 0; i < 8; i++) v[i] = __ldcs(&rp[i * 32 + lane]);

    // histogram; atomic return value IS the edge's rank within its dst bucket
    if (tid < E) {
        g_rkb[tid] = atomicAdd(&g_cntb[eb[E + tid]], 1);
        g_rkf[tid] = atomicAdd(&g_cntf[ef[E + tid]], 1);
    }

    float ss = 0.f, mx = 0.f;
    #pragma unroll
    for (int i = 0; i < 8; i++) {
        float4 a = v[i];
        ss += a.x*a.x + a.y*a.y + a.z*a.z + a.w*a.w;
        mx = fmaxf(mx, fmaxf(fmaxf(fabsf(a.x), fabsf(a.y)), fmaxf(fabsf(a.z), fabsf(a.w))));
    }
    #pragma unroll
    for (int o = 16; o; o >>= 1) {
        ss += __shfl_xor_sync(0xffffffffu, ss, o);
        mx = fmaxf(mx, __shfl_xor_sync(0xffffffffu, mx, o));
    }
    if (lane == 0) { s_ss[wrp] = ss; s_mx[wrp] = mx; }
    __syncthreads();
    const int pair = wrp & ~1;
    const float ssT = s_ss[pair] + s_ss[pair + 1];
    const float mxT = fmaxf(fmaxf(s_mx[pair], s_mx[pair + 1]), 1e-20f);
    const float qs = 127.f / mxT;

    unsigned int* o = (unsigned int*)g_qb + (size_t)row * 512 + half * 256;
    #pragma unroll
    for (int i = 0; i < 8; i++) o[i * 32 + lane] = pack4(v[i], qs);
    if (half == 0 && lane == 0)
        g_scb[row] = mxT * rsqrtf(ssT + 1e-8f) * (1.f / 127.f);
}

// ---------------- single-kernel scan (256 blocks x 256) ---------------------
__global__ void __launch_bounds__(256) k_scan1()
{
    const int list = blockIdx.x >> 7;          // 0 body, 1 face
    const int blk  = blockIdx.x & 127;
    const int t = threadIdx.x;
    const int lane = t & 31, wrp = t >> 5;
    const int* cnt = list ? g_cntf : g_cntb;
    int* off = list ? g_offf : g_offb;

    // (1) block prefix: sum of cnt[0 .. blk*256)
    int pre = 0;
    const int lim = blk * 256;
    for (int i = t; i < lim; i += 256) pre += cnt[i];
    #pragma unroll
    for (int o = 16; o; o >>= 1) pre += __shfl_xor_sync(0xffffffffu, pre, o);
    __shared__ int wpres[8];
    if (lane == 0) wpres[wrp] = pre;
    __syncthreads();
    int spre = 0;
    #pragma unroll
    for (int w = 0; w < 8; w++) spre += wpres[w];

    // (2) local exclusive scan of this block's 256 counts
    const int idx = blk * 256 + t;
    const int v = cnt[idx];
    int x = v;
    #pragma unroll
    for (int o = 1; o < 32; o <<= 1) {
        int y = __shfl_up_sync(0xffffffffu, x, o);
        if (lane >= o) x += y;
    }
    __shared__ int wsum[8];
    if (lane == 31) wsum[wrp] = x;
    __syncthreads();
    int wpre = 0;
    #pragma unroll
    for (int w = 0; w < 8; w++) wpre += (w < wrp) ? wsum[w] : 0;

    off[idx] = spre + wpre + x - v;
    if (blk == 127 && t == 255) off[N_NODES] = spre + wpre + x;
}

// ---------------- K3F: face norm+quant + atomic-free edge scatter ----------
// grid = N_NODES/8 blocks x 256 (tid count == E exactly).
__global__ void __launch_bounds__(256) k3f_norm(const float* __restrict__ vis,
                                                const int* __restrict__ eb,
                                                const int* __restrict__ ef, int E)
{
    const int t = threadIdx.x;
    const int tid = blockIdx.x * 256 + t;
    const int wrp = t >> 5, lane = t & 31;
    const int row = blockIdx.x * 8 + wrp;

    const float4* rp = (const float4*)(vis + (size_t)row * VFDIM);
    float4 v[4];
    #pragma unroll
    for (int i = 0; i < 4; i++) v[i] = __ldcs(&rp[i * 32 + lane]);

    // scatter: position = off[dst] + precomputed rank (no atomics)
    if (tid < E) {
        const int sb = eb[tid], db = eb[E + tid];
        g_esb[__ldg(&g_offb[db]) + g_rkb[tid]] = sb;
        const int sf = ef[tid], df = ef[E + tid];
        g_esf[__ldg(&g_offf[df]) + g_rkf[tid]] = sf;
    }

    float ss = 0.f, mx = 0.f;
    #pragma unroll
    for (int i = 0; i < 4; i++) {
        float4 a = v[i];
        ss += a.x*a.x + a.y*a.y + a.z*a.z + a.w*a.w;
        mx = fmaxf(mx, fmaxf(fmaxf(fabsf(a.x), fabsf(a.y)), fmaxf(fabsf(a.z), fabsf(a.w))));
    }
    #pragma unroll
    for (int o = 16; o; o >>= 1) {
        ss += __shfl_xor_sync(0xffffffffu, ss, o);
        mx = fmaxf(mx, __shfl_xor_sync(0xffffffffu, mx, o));
    }
    mx = fmaxf(mx, 1e-20f);
    const float qs = 127.f / mx;
    unsigned int* o = (unsigned int*)g_qf + (size_t)row * 128;
    #pragma unroll
    for (int i = 0; i < 4; i++) o[i * 32 + lane] = pack4(v[i], qs);
    if (lane == 0) g_scf[row] = mx * rsqrtf(ss + 1e-8f) * (1.f / 127.f);
}

// ---------------- K4: per-node BN + PReLU + 3 scalar projections -----------
__global__ void k4_node(const float* __restrict__ Wv,
                        const float* __restrict__ gamma,
                        const float* __restrict__ beta,
                        const float* __restrict__ prelu_a)
{
    __shared__ float A0[HIDDEN], A1[HIDDEN], D[HIDDEN];
    __shared__ float U0[HIDDEN], UB[HIDDEN], UF[HIDDEN];
    const int t = threadIdx.x; // 256

    const double invN = 1.0 / (double)N_NODES;
    const double m0 = g_stats[0] * invN, m1 = g_stats[1] * invN;
    const double C00 = g_stats[2] * invN - m0 * m0;
    const double C01 = g_stats[3] * invN - m0 * m1;
    const double C11 = g_stats[4] * invN - m1 * m1;

    for (int h = t; h < HIDDEN; h += 256) {
        const float w0 = Wv[h], w1 = Wv[HIDDEN + h];
        const float var = (float)((double)w0 * w0 * C00 + 2.0 * w0 * w1 * C01 + (double)w1 * w1 * C11);
        const float mu  = (float)((double)w0 * m0 + (double)w1 * m1);
        const float gg  = gamma[h] * rsqrtf(var + 1e-5f);
        A0[h] = w0 * gg;
        A1[h] = w1 * gg;
        D[h]  = beta[h] - mu * gg;
        U0[h] = g_u0[h]; UB[h] = g_ub[h]; UF[h] = g_uf[h];
    }
    __syncthreads();

    const int n = blockIdx.x * 256 + t;
    const float2 y = g_y[n];
    const float aa = prelu_a[0];
    float acc0 = 0.f, accb = 0.f, accf = 0.f;
    #pragma unroll 8
    for (int h = 0; h < HIDDEN; h++) {
        float v = fmaf(A0[h], y.x, fmaf(A1[h], y.y, D[h]));
        v = (v >= 0.f) ? v : aa * v;
        acc0 = fmaf(v, U0[h], acc0);
        accb = fmaf(v, UB[h], accb);
        accf = fmaf(v, UF[h], accf);
    }
    g_score0[n] = acc0 + g_c[0];
    g_ssb[n]    = (accb + g_c[1]) * g_scb[n];
    g_ssf[n]    = (accf + g_c[2]) * g_scf[n];
}

// ---------------- K5 core: dst-grouped int8 cosine message passing ----------
template<int ROWI4>
__device__ __forceinline__ void k5_core(int wid, int lane,
                                        const int4*  __restrict__ q,
                                        const int*   __restrict__ off,
                                        const int*   __restrict__ sorted,
                                        const float* __restrict__ ss,
                                        const float* __restrict__ sc,
                                        float*       __restrict__ msg)
{
    constexpr int C = ROWI4 / 32;
    int4 dreg[C];
    #pragma unroll
    for (int c = 0; c < C; c++)
        dreg[c] = q[(size_t)wid * ROWI4 + c * 32 + lane];

    const int start = off[wid], end = off[wid + 1];
    float fl = 0.f;
    int e = start;
    for (; e + 1 < end; e += 2) {
        const int s0 = sorted[e];
        const int s1 = sorted[e + 1];
        const int4* p0 = q + (size_t)s0 * ROWI4 + lane;
        const int4* p1 = q + (size_t)s1 * ROWI4 + lane;
        int id0 = 0, id1 = 0;
        #pragma unroll
        for (int c = 0; c < C; c++) {
            int4 a = __ldcg(&p0[c * 32]);
            int4 b = __ldcg(&p1[c * 32]);
            id0 = __dp4a(a.x, dreg[c].x, id0);
            id0 = __dp4a(a.y, dreg[c].y, id0);
            id0 = __dp4a(a.z, dreg[c].z, id0);
            id0 = __dp4a(a.w, dreg[c].w, id0);
            id1 = __dp4a(b.x, dreg[c].x, id1);
            id1 = __dp4a(b.y, dreg[c].y, id1);
            id1 = __dp4a(b.z, dreg[c].z, id1);
            id1 = __dp4a(b.w, dreg[c].w, id1);
        }
        fl = fmaf((float)id0, __ldg(&ss[s0]), fl);
        fl = fmaf((float)id1, __ldg(&ss[s1]), fl);
    }
    if (e < end) {
        const int s0 = sorted[e];
        const int4* p0 = q + (size_t)s0 * ROWI4 + lane;
        int id0 = 0;
        #pragma unroll
        for (int c = 0; c < C; c++) {
            int4 a = __ldcg(&p0[c * 32]);
            id0 = __dp4a(a.x, dreg[c].x, id0);
            id0 = __dp4a(a.y, dreg[c].y, id0);
            id0 = __dp4a(a.z, dreg[c].z, id0);
            id0 = __dp4a(a.w, dreg[c].w, id0);
        }
        fl = fmaf((float)id0, __ldg(&ss[s0]), fl);
    }
    for (int o = 16; o; o >>= 1) fl += __shfl_down_sync(0xffffffffu, fl, o);
    if (lane == 0) msg[wid] = fl * sc[wid];
}

// Union launch: warps [0, N) body, [N, 2N) face — face backfills body tail.
__global__ void __launch_bounds__(256) k5_union()
{
    const int lane = threadIdx.x & 31;
    const int gw = (blockIdx.x * 256 + threadIdx.x) >> 5;   // global warp id
    if (gw < N_NODES) {
        k5_core<VBDIM / 16>(gw, lane, g_qb, g_offb, g_esb, g_ssb, g_scb, g_msgb);
    } else {
        k5_core<VFDIM / 16>(gw - N_NODES, lane, g_qf, g_offf, g_esf, g_ssf, g_scf, g_msgf);
    }
}

// ---------------- K6: final combine ----------------------------------------
__global__ void k6_final(float* __restrict__ out)
{
    const int n = blockIdx.x * 256 + threadIdx.x;
    const float db = (float)(g_offb[n + 1] - g_offb[n]);
    const float df = (float)(g_offf[n + 1] - g_offf[n]);
    out[n] = g_score0[n]
           + g_msgb[n] / fmaxf(db, 1.0f)
           + g_msgf[n] / fmaxf(df, 1.0f);
}

// ---------------- launch ----------------------------------------------------
extern "C" void kernel_launch(void* const* d_in, const int* in_sizes, int n_in,
                              void* d_out, int out_size)
{
    const float* x        = (const float*)d_in[0];
    const float* vis_body = (const float*)d_in[1];
    const float* vis_face = (const float*)d_in[2];
    const int*   edge_b   = (const int*)d_in[3];
    const int*   edge_f   = (const int*)d_in[4];
    const int E = in_sizes[3] / 2;

    int base = 5;
    if (n_in > 5 && in_sizes[5] == 1) base = 6;
    const float* Wq      = (const float*)d_in[base + 0];
    const float* Wk      = (const float*)d_in[base + 1];
    const float* Wv      = (const float*)d_in[base + 2];
    const float* gamma   = (const float*)d_in[base + 3];
    const float* beta    = (const float*)d_in[base + 4];
    const float* prelu_a = (const float*)d_in[base + 5];
    const float* Wm      = (const float*)d_in[base + 6];
    const float* bm      = (const float*)d_in[base + 7];
    const float* Wnp     = (const float*)d_in[base + 8];
    const float* bnp     = (const float*)d_in[base + 9];
    const float* Wb_root = (const float*)d_in[base + 10];
    const float* Wb_msg  = (const float*)d_in[base + 11];
    const float* bb      = (const float*)d_in[base + 12];
    const float* Wf_root = (const float*)d_in[base + 13];
    const float* Wf_msg  = (const float*)d_in[base + 14];
    const float* bf      = (const float*)d_in[base + 15];
    const float* Wpb     = (const float*)d_in[base + 16];
    const float* bpb     = (const float*)d_in[base + 17];
    const float* Wpf     = (const float*)d_in[base + 18];
    const float* bpf     = (const float*)d_in[base + 19];

    k1_precompute<<<1, 512>>>(Wq, Wk, Wm, bm, Wnp, bnp,
                              Wb_root, Wb_msg, bb, Wf_root, Wf_msg, bf,
                              Wpb, bpb, Wpf, bpf);                   // + zero counters
    k3b_mega<<<128 + N_NODES / 4, 256>>>(vis_body, x, edge_b, edge_f, E); // attn + norm + hist/rank
    k_scan1<<<256, 256>>>();
    k3f_norm<<<N_NODES / 8, 256>>>(vis_face, edge_b, edge_f, E);     // + atomic-free scatter
    k4_node<<<N_NODES / 256, 256>>>(Wv, gamma, beta, prelu_a);
    k5_union<<<N_NODES / 4, 256>>>();                                // body + face
    k6_final<<<N_NODES / 256, 256>>>((float*)d_out);
}